// round 11
// baseline (speedup 1.0000x reference)
#include <cuda_runtime.h>
#include <cuda_fp16.h>

// ---------------------------------------------------------------------------
// Exact-rank 5x5 median filter, fp32 in/out, symmetric (reflect) padding.
//   * packed fp16 comparators (HMNMX2); lanes = TWO VERTICAL WINDOWS (A,B)
//     of the same plane -> column stage + sel13 run ONCE per 2 output rows
//   * ring P_i = (row t-2+i, row t-1+i); one packed sort per 2 new rows
//   * doubly-sorted matrix pruning: median(25) = rank-7 of 13 candidates
//   * x4096 fp32 pre-scale avoids fp16 denormals; /4096 on output (exact pow2)
// ---------------------------------------------------------------------------

typedef __half2 h2;

__device__ __forceinline__ void cex(h2& a, h2& b) {
    h2 mn = __hmin2(a, b);
    b = __hmax2(a, b);
    a = mn;
}

// symmetric reflect for pad<=2 on either side (valid for |overhang| < n)
__device__ __forceinline__ int refl(int i, int n) {
    i = (i < 0) ? (-1 - i) : i;
    i = (i >= n) ? (2 * n - 1 - i) : i;
    return i;
}

constexpr int IMG_H   = 512;
constexpr int IMG_W   = 512;
constexpr int PLANES  = 16 * 3;           // 48
constexpr int TROWS   = 16;               // output rows per thread
constexpr int STEPS   = TROWS / 2;        // 8 (2 rows per step)
constexpr int STRIPS  = IMG_H / TROWS;    // 32
constexpr int PSTRIDE = IMG_H * IMG_W;

constexpr float SCALE     = 4096.0f;
constexpr float INV_SCALE = 1.0f / 4096.0f;

// 5 taps of one image row (single plane)
__device__ __forceinline__ void load_row(const float* __restrict__ row,
                                         int xm2, int xm1, int x, int xp1, int xp2,
                                         float a[5]) {
    a[0] = __ldg(row + xm2); a[1] = __ldg(row + xm1); a[2] = __ldg(row + x);
    a[3] = __ldg(row + xp1); a[4] = __ldg(row + xp2);
}

// pack (rowLo -> lane0, rowHi -> lane1), scale, and 9-CE sort5 both lanes
__device__ __forceinline__ void pack_sort(const float lo[5], const float hi[5], h2 o[5]) {
    #pragma unroll
    for (int k = 0; k < 5; k++)
        o[k] = __floats2half2_rn(lo[k] * SCALE, hi[k] * SCALE);
    cex(o[0], o[1]); cex(o[3], o[4]); cex(o[2], o[4]); cex(o[2], o[3]);
    cex(o[0], o[3]); cex(o[0], o[2]); cex(o[1], o[4]); cex(o[1], o[3]); cex(o[1], o[2]);
}

// rank-7 of the 13 pruned candidates (verified R4..R10)
__device__ __forceinline__ h2 sel13(h2 a3, h2 a4, h2 b2, h2 b3, h2 b4,
                                    h2 c1, h2 c2, h2 c3,
                                    h2 d0, h2 d1, h2 d2, h2 e0, h2 e1) {
    // U = merge((d0,e0),(c1,d1,e1)) -> sorted 5
    h2 s0 = __hmin2(d0, c1), t0 = __hmax2(d0, c1);
    h2 v1 = __hmin2(t0, e1), v2 = __hmax2(t0, e1);
    h2 w0 = __hmin2(e0, d1), w1 = __hmax2(e0, d1);
    h2 U0 = s0;
    h2 U1 = __hmin2(v1, w0), U2 = __hmax2(v1, w0);
    h2 U3 = __hmin2(v2, w1), U4 = __hmax2(v2, w1);

    // V = merge((a3,b3,c3),(a4,b4)) -> sorted 5
    h2 m0 = __hmin2(a3, a4), h0 = __hmax2(a3, a4);
    h2 o1 = __hmin2(h0, c3), o2 = __hmax2(h0, c3);
    h2 p0 = __hmin2(b3, b4), p1 = __hmax2(b3, b4);
    h2 V0 = m0;
    h2 V1 = __hmin2(o1, p0), V2 = __hmax2(o1, p0);
    h2 V3 = __hmin2(o2, p1), V4 = __hmax2(o2, p1);

    // W = merge(U(5), (b2,c2,d2)) -> sorted 8, lanes W1..W6 only
    h2 hh  = __hmax2(U0, b2);
    h2 oo1 = __hmin2(hh, U4), oo2 = __hmax2(hh, U4);
    h2 qq0 = __hmin2(U2, d2), qq1 = __hmax2(U2, d2);
    h2 O1 = __hmin2(oo1, qq0), O2 = __hmax2(oo1, qq0);
    h2 O3 = __hmin2(oo2, qq1);
    h2 m2 = __hmin2(U1, c2), h2v = __hmax2(U1, c2);
    h2 E0 = m2;
    h2 E1 = __hmin2(h2v, U3), E2 = __hmax2(h2v, U3);
    h2 W1 = __hmin2(O1, E0), W2 = __hmax2(O1, E0);
    h2 W3 = __hmin2(O2, E1), W4 = __hmax2(O2, E1);
    h2 W5 = __hmin2(O3, E2), W6 = __hmax2(O3, E2);

    // rank-7 of union(W sorted 8, V sorted 5)
    h2 med = W6;
    med = __hmin2(med, __hmax2(W1, V4));
    med = __hmin2(med, __hmax2(W2, V3));
    med = __hmin2(med, __hmax2(W3, V2));
    med = __hmin2(med, __hmax2(W4, V1));
    med = __hmin2(med, __hmax2(W5, V0));
    return med;
}

// median over 5 sorted (lane-parallel) rows R0..R4 via doubly-sorted-matrix
// pruning with explicit partial-rank column networks (verified R7/R9).
__device__ __forceinline__ h2 median25(const h2 (&R0)[5], const h2 (&R1)[5],
                                       const h2 (&R2)[5], const h2 (&R3)[5],
                                       const h2 (&R4)[5]) {
    // ---- col 0: top-2 -> a3,a4 ----
    h2 a3, a4;
    {
        h2 p = R0[0], q = R1[0], rr = R2[0], ss = R3[0], e = R4[0];
        h2 h1 = __hmax2(p, q),  l1 = __hmin2(p, q);
        h2 hB = __hmax2(rr, ss), lB = __hmin2(rr, ss);
        h2 t4 = __hmax2(h1, hB);
        h2 t3 = __hmax2(__hmin2(h1, hB), __hmax2(l1, lB));
        a4 = __hmax2(e, t4);
        a3 = __hmax2(__hmin2(e, t4), t3);
    }
    // ---- col 4: bottom-2 -> e0,e1 ----
    h2 e0, e1;
    {
        h2 p = R0[4], q = R1[4], rr = R2[4], ss = R3[4], e = R4[4];
        h2 h1 = __hmax2(p, q),  l1 = __hmin2(p, q);
        h2 hB = __hmax2(rr, ss), lB = __hmin2(rr, ss);
        h2 t0 = __hmin2(l1, lB);
        h2 t1 = __hmin2(__hmax2(l1, lB), __hmin2(h1, hB));
        e0 = __hmin2(e, t0);
        e1 = __hmin2(__hmax2(e, t0), t1);
    }
    // ---- col 1: top-3 -> b2,b3,b4 ----
    h2 b2, b3, b4;
    {
        h2 p = R0[1], q = R1[1], rr = R2[1], ss = R3[1], e = R4[1];
        h2 lo1 = __hmin2(p, q),  hi1 = __hmax2(p, q);
        h2 lo2 = __hmin2(rr, ss), hi2 = __hmax2(rr, ss);
        h2 s3 = __hmax2(hi1, hi2);
        h2 bm = __hmin2(hi1, hi2), cm = __hmax2(lo1, lo2);
        h2 s1 = __hmin2(bm, cm), s2 = __hmax2(bm, cm);
        b4 = __hmax2(e, s3);
        h2 m = __hmin2(e, s3);
        b3 = __hmax2(m, s2);
        h2 m2 = __hmin2(m, s2);
        b2 = __hmax2(m2, s1);
    }
    // ---- col 3: bottom-3 -> d0,d1,d2 ----
    h2 d0, d1, d2;
    {
        h2 p = R0[3], q = R1[3], rr = R2[3], ss = R3[3], e = R4[3];
        h2 lo1 = __hmin2(p, q),  hi1 = __hmax2(p, q);
        h2 lo2 = __hmin2(rr, ss), hi2 = __hmax2(rr, ss);
        h2 s0 = __hmin2(lo1, lo2);
        h2 cm = __hmax2(lo1, lo2), bm = __hmin2(hi1, hi2);
        h2 s1 = __hmin2(cm, bm), s2 = __hmax2(cm, bm);
        d0 = __hmin2(e, s0);
        h2 m = __hmax2(e, s0);
        d1 = __hmin2(m, s1);
        h2 m2 = __hmax2(m, s1);
        d2 = __hmin2(m2, s2);
    }
    // ---- col 2: middle-3 -> c1,c2,c3 ----
    h2 c1, c2, c3;
    {
        h2 s0 = R0[2], s1 = R1[2], s2 = R2[2], s3 = R3[2], e = R4[2];
        cex(s0, s1); cex(s2, s3); cex(s0, s2); cex(s1, s3); cex(s1, s2);   // sort4
        h2 u = __hmax2(e, s0);
        c1 = __hmin2(u, s1); u = __hmax2(u, s1);
        c2 = __hmin2(u, s2); u = __hmax2(u, s2);
        c3 = __hmin2(u, s3);
    }
    return sel13(a3, a4, b2, b3, b4, c1, c2, c3, d0, d1, d2, e0, e1);
}

__global__ void __launch_bounds__(128, 6)
median5x5_kernel(const float* __restrict__ src, float* __restrict__ dst) {
    const int tid   = blockIdx.x * blockDim.x + threadIdx.x;
    const int x     = tid & (IMG_W - 1);
    const int rest  = tid >> 9;                 // / 512
    const int strip = rest & (STRIPS - 1);      // % 32
    const int plane = rest >> 5;                // / 32
    if (plane >= PLANES) return;

    const float* sP = src + (size_t)plane * PSTRIDE;
    float*       dP = dst + (size_t)plane * PSTRIDE;

    const int xm2 = refl(x - 2, IMG_W);
    const int xm1 = refl(x - 1, IMG_W);
    const int xp1 = refl(x + 1, IMG_W);
    const int xp2 = refl(x + 2, IMG_W);
    const int y0  = strip * TROWS;

    // Ring of 5 packed rows. At step s (base b = 2s mod 5):
    //   window-row i = P[(b+i)%5], lane0 = row(y0+2s-2+i), lane1 = row(y0+2s-1+i)
    h2 P[5][5];

    {   // init: rows y0-2 .. y0+3, P[i] = pack(row i, row i+1)
        float raw[6][5];
        #pragma unroll
        for (int i = 0; i < 6; i++)
            load_row(sP + refl(y0 - 2 + i, IMG_H) * IMG_W, xm2, xm1, x, xp1, xp2, raw[i]);
        #pragma unroll
        for (int i = 0; i < 5; i++)
            pack_sort(raw[i], raw[i + 1], P[i]);
    }

    #pragma unroll
    for (int s = 0; s < STEPS; s++) {
        const int b = (2 * s) % 5;              // compile-time per unrolled iter

        h2 med = median25(P[b], P[(b + 1) % 5], P[(b + 2) % 5],
                          P[(b + 3) % 5], P[(b + 4) % 5]);

        const int yA = y0 + 2 * s;
        dP[yA * IMG_W + x]       = __low2float(med)  * INV_SCALE;   // window A
        dP[(yA + 1) * IMG_W + x] = __high2float(med) * INV_SCALE;   // window B

        if (s < STEPS - 1) {
            // load rows yA+4, yA+5; sort once as a packed pair
            float a[5], c[5];
            load_row(sP + refl(yA + 4, IMG_H) * IMG_W, xm2, xm1, x, xp1, xp2, a);
            load_row(sP + refl(yA + 5, IMG_H) * IMG_W, xm2, xm1, x, xp1, xp2, c);
            h2 N[5];
            pack_sort(a, c, N);

            // new P_3 = (lane1 of old P_4, lane0 of N); new P_4 = N
            // old P_4 lives at (b+4)%5; dead slots (b)%5, (b+1)%5 receive them
            #pragma unroll
            for (int k = 0; k < 5; k++) {
                P[b][k] = __halves2half2(__high2half(P[(b + 4) % 5][k]),
                                         __low2half(N[k]));
                P[(b + 1) % 5][k] = N[k];
            }
        }
    }
}

extern "C" void kernel_launch(void* const* d_in, const int* in_sizes, int n_in,
                              void* d_out, int out_size) {
    (void)in_sizes; (void)n_in; (void)out_size;
    const float* src = (const float*)d_in[0];
    float*       dst = (float*)d_out;

    const int total_threads = PLANES * IMG_W * STRIPS;   // 786432
    const int block = 128;
    const int grid  = total_threads / block;             // 6144
    median5x5_kernel<<<grid, block>>>(src, dst);
}

// round 12
// speedup vs baseline: 1.1979x; 1.1979x over previous
#include <cuda_runtime.h>
#include <cuda_fp16.h>

// ---------------------------------------------------------------------------
// Exact-rank 5x5 median filter, fp32 in/out, symmetric (reflect) padding.
//   * packed fp16 comparators (HMNMX2): lanes = 2 image planes
//   * vertical row-pairing (median2): two outputs share column-stage work
//   * warp-uniform interior/edge strip split: interior strips use pure
//     immediate-offset LDG/STG (tap base pointers, compile-time row offsets)
//   * doubly-sorted matrix pruning: median(25) = rank-7 of 13 candidates
//   * x4096 fp32 pre-scale avoids fp16 denormals; /4096 on output (exact pow2)
// ---------------------------------------------------------------------------

typedef __half2 h2;

__device__ __forceinline__ void cex(h2& a, h2& b) {
    h2 mn = __hmin2(a, b);
    b = __hmax2(a, b);
    a = mn;
}

__device__ __forceinline__ void sort4(h2& a, h2& b, h2& c, h2& d) {
    cex(a, b); cex(c, d); cex(a, c); cex(b, d); cex(b, c);
}

// symmetric reflect for pad<=2:  -1->0, -2->1, N->N-1, N+1->N-2
__device__ __forceinline__ int refl(int i, int n) {
    i = (i < 0) ? (-1 - i) : i;
    i = (i >= n) ? (2 * n - 1 - i) : i;
    return i;
}

constexpr int IMG_H   = 512;
constexpr int IMG_W   = 512;
constexpr int PLANES  = 16 * 3;           // 48
constexpr int PAIRS   = PLANES / 2;       // 24 packed plane-pairs
constexpr int TROWS   = 16;               // output rows per thread
constexpr int STRIPS  = IMG_H / TROWS;    // 32
constexpr int PSTRIDE = IMG_H * IMG_W;

constexpr float SCALE     = 4096.0f;
constexpr float INV_SCALE = 1.0f / 4096.0f;

struct Taps { const float *p0, *p1, *p2, *p3, *p4; };

// Load both planes' 5 taps of row (y0+rel).
// Interior: base-pointer + compile-time immediate (rel, PSTRIDE constants).
// Edge: reflected row index, generic addressing.
template <bool EDGE>
__device__ __forceinline__ void load_row2(const Taps& T, const float* __restrict__ sA,
                                          int y0, int rel,
                                          int xm2, int xm1, int xc, int xp1, int xp2,
                                          float a[5], float b[5]) {
    if (!EDGE) {
        const int off = rel * IMG_W;
        a[0] = __ldg(T.p0 + off); a[1] = __ldg(T.p1 + off); a[2] = __ldg(T.p2 + off);
        a[3] = __ldg(T.p3 + off); a[4] = __ldg(T.p4 + off);
        const int offb = off + PSTRIDE;
        b[0] = __ldg(T.p0 + offb); b[1] = __ldg(T.p1 + offb); b[2] = __ldg(T.p2 + offb);
        b[3] = __ldg(T.p3 + offb); b[4] = __ldg(T.p4 + offb);
    } else {
        const float* row = sA + refl(y0 + rel, IMG_H) * IMG_W;
        a[0] = __ldg(row + xm2); a[1] = __ldg(row + xm1); a[2] = __ldg(row + xc);
        a[3] = __ldg(row + xp1); a[4] = __ldg(row + xp2);
        const float* rb = row + PSTRIDE;
        b[0] = __ldg(rb + xm2); b[1] = __ldg(rb + xm1); b[2] = __ldg(rb + xc);
        b[3] = __ldg(rb + xp1); b[4] = __ldg(rb + xp2);
    }
}

// scale + pack + optimal 9-CE sort5
__device__ __forceinline__ void cvt_sort(const float a[5], const float b[5], h2 o[5]) {
    #pragma unroll
    for (int k = 0; k < 5; k++)
        o[k] = __floats2half2_rn(a[k] * SCALE, b[k] * SCALE);
    cex(o[0], o[1]); cex(o[3], o[4]); cex(o[2], o[4]); cex(o[2], o[3]);
    cex(o[0], o[3]); cex(o[0], o[2]); cex(o[1], o[4]); cex(o[1], o[3]); cex(o[1], o[2]);
}

// rank-7 of the 13 pruned candidates (verified R4..R10)
__device__ __forceinline__ h2 sel13(h2 a3, h2 a4, h2 b2, h2 b3, h2 b4,
                                    h2 c1, h2 c2, h2 c3,
                                    h2 d0, h2 d1, h2 d2, h2 e0, h2 e1) {
    h2 s0 = __hmin2(d0, c1), t0 = __hmax2(d0, c1);
    h2 v1 = __hmin2(t0, e1), v2 = __hmax2(t0, e1);
    h2 w0 = __hmin2(e0, d1), w1 = __hmax2(e0, d1);
    h2 U0 = s0;
    h2 U1 = __hmin2(v1, w0), U2 = __hmax2(v1, w0);
    h2 U3 = __hmin2(v2, w1), U4 = __hmax2(v2, w1);

    h2 m0 = __hmin2(a3, a4), h0 = __hmax2(a3, a4);
    h2 o1 = __hmin2(h0, c3), o2 = __hmax2(h0, c3);
    h2 p0 = __hmin2(b3, b4), p1 = __hmax2(b3, b4);
    h2 V0 = m0;
    h2 V1 = __hmin2(o1, p0), V2 = __hmax2(o1, p0);
    h2 V3 = __hmin2(o2, p1), V4 = __hmax2(o2, p1);

    h2 hh  = __hmax2(U0, b2);
    h2 oo1 = __hmin2(hh, U4), oo2 = __hmax2(hh, U4);
    h2 qq0 = __hmin2(U2, d2), qq1 = __hmax2(U2, d2);
    h2 O1 = __hmin2(oo1, qq0), O2 = __hmax2(oo1, qq0);
    h2 O3 = __hmin2(oo2, qq1);
    h2 m2 = __hmin2(U1, c2), h2v = __hmax2(U1, c2);
    h2 E0 = m2;
    h2 E1 = __hmin2(h2v, U3), E2 = __hmax2(h2v, U3);
    h2 W1 = __hmin2(O1, E0), W2 = __hmax2(O1, E0);
    h2 W3 = __hmin2(O2, E1), W4 = __hmax2(O2, E1);
    h2 W5 = __hmin2(O3, E2), W6 = __hmax2(O3, E2);

    h2 med = W6;
    med = __hmin2(med, __hmax2(W1, V4));
    med = __hmin2(med, __hmax2(W2, V3));
    med = __hmin2(med, __hmax2(W3, V2));
    med = __hmin2(med, __hmax2(W4, V1));
    med = __hmin2(med, __hmax2(W5, V0));
    return med;
}

// Two medians (consecutive output rows) from 6 sorted rows R0..R5 (verified R5/R9).
__device__ __forceinline__ void median2(
    const h2 (&R0)[5], const h2 (&R1)[5], const h2 (&R2)[5],
    const h2 (&R3)[5], const h2 (&R4)[5], const h2 (&R5)[5],
    h2& medA, h2& medB)
{
    h2 a3A, a4A, a3B, a4B;
    {
        h2 p = R1[0], q = R2[0], rr = R3[0], ss = R4[0];
        h2 h1 = __hmax2(p, q), l1 = __hmin2(p, q);
        h2 hB = __hmax2(rr, ss), lB = __hmin2(rr, ss);
        h2 s3 = __hmax2(h1, hB);
        h2 s2 = __hmax2(__hmin2(h1, hB), __hmax2(l1, lB));
        h2 eA = R0[0], eB = R5[0];
        a4A = __hmax2(eA, s3); a3A = __hmax2(__hmin2(eA, s3), s2);
        a4B = __hmax2(eB, s3); a3B = __hmax2(__hmin2(eB, s3), s2);
    }
    h2 e0A, e1A, e0B, e1B;
    {
        h2 p = R1[4], q = R2[4], rr = R3[4], ss = R4[4];
        h2 h1 = __hmax2(p, q), l1 = __hmin2(p, q);
        h2 hB = __hmax2(rr, ss), lB = __hmin2(rr, ss);
        h2 s0 = __hmin2(l1, lB);
        h2 s1 = __hmin2(__hmax2(l1, lB), __hmin2(h1, hB));
        h2 eA = R0[4], eB = R5[4];
        e0A = __hmin2(eA, s0); e1A = __hmin2(__hmax2(eA, s0), s1);
        e0B = __hmin2(eB, s0); e1B = __hmin2(__hmax2(eB, s0), s1);
    }
    h2 b2A, b3A, b4A, b2B, b3B, b4B;
    {
        h2 a = R1[1], b = R2[1], c = R3[1], d = R4[1];
        cex(a, b); cex(c, d);
        h2 s3 = __hmax2(b, d), bm = __hmin2(b, d), cm = __hmax2(a, c);
        h2 s1 = __hmin2(bm, cm), s2 = __hmax2(bm, cm);
        h2 eA = R0[1], eB = R5[1];
        {
            h2 m = __hmin2(eA, s3); b4A = __hmax2(eA, s3);
            b3A = __hmax2(m, s2); h2 m2 = __hmin2(m, s2);
            b2A = __hmax2(m2, s1);
        }
        {
            h2 m = __hmin2(eB, s3); b4B = __hmax2(eB, s3);
            b3B = __hmax2(m, s2); h2 m2 = __hmin2(m, s2);
            b2B = __hmax2(m2, s1);
        }
    }
    h2 d0A, d1A, d2A, d0B, d1B, d2B;
    {
        h2 a = R1[3], b = R2[3], c = R3[3], d = R4[3];
        cex(a, b); cex(c, d);
        h2 s0 = __hmin2(a, c), cm = __hmax2(a, c), bm = __hmin2(b, d);
        h2 s1 = __hmin2(cm, bm), s2 = __hmax2(cm, bm);
        h2 eA = R0[3], eB = R5[3];
        {
            h2 m = __hmax2(eA, s0); d0A = __hmin2(eA, s0);
            d1A = __hmin2(m, s1); h2 m2 = __hmax2(m, s1);
            d2A = __hmin2(m2, s2);
        }
        {
            h2 m = __hmax2(eB, s0); d0B = __hmin2(eB, s0);
            d1B = __hmin2(m, s1); h2 m2 = __hmax2(m, s1);
            d2B = __hmin2(m2, s2);
        }
    }
    h2 c1A, c2A, c3A, c1B, c2B, c3B;
    {
        h2 a = R1[2], b = R2[2], c = R3[2], d = R4[2];
        sort4(a, b, c, d);
        h2 eA = R0[2], eB = R5[2];
        {
            h2 u = __hmax2(eA, a);
            c1A = __hmin2(u, b); u = __hmax2(u, b);
            c2A = __hmin2(u, c); u = __hmax2(u, c);
            c3A = __hmin2(u, d);
        }
        {
            h2 u = __hmax2(eB, a);
            c1B = __hmin2(u, b); u = __hmax2(u, b);
            c2B = __hmin2(u, c); u = __hmax2(u, c);
            c3B = __hmin2(u, d);
        }
    }
    medA = sel13(a3A, a4A, b2A, b3A, b4A, c1A, c2A, c3A, d0A, d1A, d2A, e0A, e1A);
    medB = sel13(a3B, a4B, b2B, b3B, b4B, c1B, c2B, c3B, d0B, d1B, d2B, e0B, e1B);
}

template <bool EDGE>
__device__ __forceinline__ void do_strip(const Taps& T, const float* __restrict__ sA,
                                         float* __restrict__ outb, int y0,
                                         int xm2, int xm1, int xc, int xp1, int xp2) {
    // Ring of 6 sorted rows; relative row i (abs y0-2+i) lives in slot i%6.
    h2 r[6][5];

    #pragma unroll
    for (int i = 0; i < 4; i++) {
        float a[5], b[5];
        load_row2<EDGE>(T, sA, y0, -2 + i, xm2, xm1, xc, xp1, xp2, a, b);
        cvt_sort(a, b, r[i]);
    }

    #pragma unroll
    for (int tp = 0; tp < TROWS / 2; tp++) {
        {
            float a0[5], b0[5], a1[5], b1[5];
            load_row2<EDGE>(T, sA, y0, 2 * tp + 2, xm2, xm1, xc, xp1, xp2, a0, b0);
            load_row2<EDGE>(T, sA, y0, 2 * tp + 3, xm2, xm1, xc, xp1, xp2, a1, b1);
            cvt_sort(a0, b0, r[(2 * tp + 4) % 6]);
            cvt_sort(a1, b1, r[(2 * tp + 5) % 6]);
        }

        h2 medA, medB;
        median2(r[(2 * tp + 0) % 6], r[(2 * tp + 1) % 6], r[(2 * tp + 2) % 6],
                r[(2 * tp + 3) % 6], r[(2 * tp + 4) % 6], r[(2 * tp + 5) % 6],
                medA, medB);

        // stores: compile-time offsets from outb (output rows never reflect)
        outb[(2 * tp) * IMG_W]                 = __low2float(medA)  * INV_SCALE;
        outb[(2 * tp) * IMG_W + PSTRIDE]       = __high2float(medA) * INV_SCALE;
        outb[(2 * tp + 1) * IMG_W]             = __low2float(medB)  * INV_SCALE;
        outb[(2 * tp + 1) * IMG_W + PSTRIDE]   = __high2float(medB) * INV_SCALE;
    }
}

__global__ void __launch_bounds__(128, 6)
median5x5_kernel(const float* __restrict__ src, float* __restrict__ dst) {
    const int tid   = blockIdx.x * blockDim.x + threadIdx.x;
    const int x     = tid & (IMG_W - 1);
    const int rest  = tid >> 9;                 // / 512
    const int strip = rest & (STRIPS - 1);      // % 32
    const int pair  = rest >> 5;                // / 32
    if (pair >= PAIRS) return;

    const float* sA = src + (size_t)(2 * pair) * PSTRIDE;
    float*       dA = dst + (size_t)(2 * pair) * PSTRIDE;

    const int xm2 = refl(x - 2, IMG_W);
    const int xm1 = refl(x - 1, IMG_W);
    const int xp1 = refl(x + 1, IMG_W);
    const int xp2 = refl(x + 2, IMG_W);
    const int y0  = strip * TROWS;

    // Tap base pointers anchored at row y0 (valid offsets -2..+17 used).
    const float* base = sA + y0 * IMG_W;
    Taps T{ base + xm2, base + xm1, base + x, base + xp1, base + xp2 };
    float* outb = dA + y0 * IMG_W + x;

    // strip index is warp-uniform (warp spans x only) -> uniform branch
    if (strip > 0 && strip < STRIPS - 1) {
        do_strip<false>(T, sA, outb, y0, xm2, xm1, x, xp1, xp2);
    } else {
        do_strip<true>(T, sA, outb, y0, xm2, xm1, x, xp1, xp2);
    }
}

extern "C" void kernel_launch(void* const* d_in, const int* in_sizes, int n_in,
                              void* d_out, int out_size) {
    (void)in_sizes; (void)n_in; (void)out_size;
    const float* src = (const float*)d_in[0];
    float*       dst = (float*)d_out;

    const int total_threads = PAIRS * IMG_W * STRIPS;   // 393216
    const int block = 128;
    const int grid  = total_threads / block;            // 3072
    median5x5_kernel<<<grid, block>>>(src, dst);
}

// round 13
// speedup vs baseline: 1.3067x; 1.0908x over previous
#include <cuda_runtime.h>
#include <cuda_fp16.h>

// ---------------------------------------------------------------------------
// Exact-rank 5x5 median filter, fp32 in/out, symmetric (reflect) padding.
//   * packed fp16 comparators (HMNMX2): lanes = 2 image planes
//   * vertical row-pairing (median2): two outputs share column-stage work
//   * warp-uniform interior/edge strip split; immediate-offset LDG/STG
//   * doubly-sorted matrix pruning: median(25) = rank-7 of 13 candidates
//   * sel13 v2: poset-pruned merges (U4=e1, V0=a3, V4=max(c3,b4), U2<=d2 free)
//   * x4096 fp32 pre-scale avoids fp16 denormals; /4096 on output (exact pow2)
// ---------------------------------------------------------------------------

typedef __half2 h2;

__device__ __forceinline__ void cex(h2& a, h2& b) {
    h2 mn = __hmin2(a, b);
    b = __hmax2(a, b);
    a = mn;
}

__device__ __forceinline__ void sort4(h2& a, h2& b, h2& c, h2& d) {
    cex(a, b); cex(c, d); cex(a, c); cex(b, d); cex(b, c);
}

// symmetric reflect for pad<=2:  -1->0, -2->1, N->N-1, N+1->N-2
__device__ __forceinline__ int refl(int i, int n) {
    i = (i < 0) ? (-1 - i) : i;
    i = (i >= n) ? (2 * n - 1 - i) : i;
    return i;
}

constexpr int IMG_H   = 512;
constexpr int IMG_W   = 512;
constexpr int PLANES  = 16 * 3;           // 48
constexpr int PAIRS   = PLANES / 2;       // 24 packed plane-pairs
constexpr int TROWS   = 16;               // output rows per thread
constexpr int STRIPS  = IMG_H / TROWS;    // 32
constexpr int PSTRIDE = IMG_H * IMG_W;

constexpr float SCALE     = 4096.0f;
constexpr float INV_SCALE = 1.0f / 4096.0f;

struct Taps { const float *p0, *p1, *p2, *p3, *p4; };

template <bool EDGE>
__device__ __forceinline__ void load_row2(const Taps& T, const float* __restrict__ sA,
                                          int y0, int rel,
                                          int xm2, int xm1, int xc, int xp1, int xp2,
                                          float a[5], float b[5]) {
    if (!EDGE) {
        const int off = rel * IMG_W;
        a[0] = __ldg(T.p0 + off); a[1] = __ldg(T.p1 + off); a[2] = __ldg(T.p2 + off);
        a[3] = __ldg(T.p3 + off); a[4] = __ldg(T.p4 + off);
        const int offb = off + PSTRIDE;
        b[0] = __ldg(T.p0 + offb); b[1] = __ldg(T.p1 + offb); b[2] = __ldg(T.p2 + offb);
        b[3] = __ldg(T.p3 + offb); b[4] = __ldg(T.p4 + offb);
    } else {
        const float* row = sA + refl(y0 + rel, IMG_H) * IMG_W;
        a[0] = __ldg(row + xm2); a[1] = __ldg(row + xm1); a[2] = __ldg(row + xc);
        a[3] = __ldg(row + xp1); a[4] = __ldg(row + xp2);
        const float* rb = row + PSTRIDE;
        b[0] = __ldg(rb + xm2); b[1] = __ldg(rb + xm1); b[2] = __ldg(rb + xc);
        b[3] = __ldg(rb + xp1); b[4] = __ldg(rb + xp2);
    }
}

// scale + pack + optimal 9-CE sort5
__device__ __forceinline__ void cvt_sort(const float a[5], const float b[5], h2 o[5]) {
    #pragma unroll
    for (int k = 0; k < 5; k++)
        o[k] = __floats2half2_rn(a[k] * SCALE, b[k] * SCALE);
    cex(o[0], o[1]); cex(o[3], o[4]); cex(o[2], o[4]); cex(o[2], o[3]);
    cex(o[0], o[3]); cex(o[0], o[2]); cex(o[1], o[4]); cex(o[1], o[3]); cex(o[1], o[2]);
}

// sel13 v2: rank-7 of the 13 pruned candidates, using BOTH row chains and
// column/row-rank poset relations. Exactness of each shortcut:
//   U4 = e1      since e1 >= d1, e0, c1, d0 (column+row chains)
//   V0 = a3      since a3 <= b3<=c3 and a3 <= a4 <= b4
//   V4 = max(c3,b4)  since b3<=c3 and a4<=b4
//   sort(U2,d2) = (U2,d2) since U2 <= t <= d2 (d0<=d2, c1<=c2<=d2, m2<=d1<=d2)
__device__ __forceinline__ h2 sel13(h2 a3, h2 a4, h2 b2, h2 b3, h2 b4,
                                    h2 c1, h2 c2, h2 c3,
                                    h2 d0, h2 d1, h2 d2, h2 e0, h2 e1) {
    // U = merge((d0,e0),(c1,d1,e1)) -> sorted 5, exploiting d0<=d1, e0<=e1
    h2 U0 = __hmin2(d0, c1), M1 = __hmax2(d0, c1);
    h2 m2 = __hmin2(e0, d1), M2 = __hmax2(e0, d1);
    h2 U1 = __hmin2(M1, m2), t  = __hmax2(M1, m2);
    h2 U2 = __hmin2(t, M2),  U3 = __hmax2(t, M2);
    // U4 = e1 (free)

    // V = merge((a3,b3,c3),(a4,b4)) -> sorted 5, exploiting a3<=a4, b3<=b4
    h2 V0 = a3;
    h2 V1 = __hmin2(b3, a4), vt = __hmax2(b3, a4);
    h2 vm = __hmin2(c3, b4), V4 = __hmax2(c3, b4);
    h2 V2 = __hmin2(vt, vm), V3 = __hmax2(vt, vm);

    // W = merge(U(5), (b2,c2,d2)) -> sorted 8, lanes W1..W6 only
    //   odd lanes: merge((U0,U2,e1),(b2,d2)); sort(U2,d2) is free
    h2 hh  = __hmax2(U0, b2);
    h2 oo1 = __hmin2(hh, e1), oo2 = __hmax2(hh, e1);
    h2 O1 = __hmin2(oo1, U2), O2 = __hmax2(oo1, U2);
    h2 O3 = __hmin2(oo2, d2);
    //   even lanes: merge((U1,U3),(c2))
    h2 E0 = __hmin2(U1, c2), h2v = __hmax2(U1, c2);
    h2 E1 = __hmin2(h2v, U3), E2 = __hmax2(h2v, U3);
    //   combine
    h2 W1 = __hmin2(O1, E0), W2 = __hmax2(O1, E0);
    h2 W3 = __hmin2(O2, E1), W4 = __hmax2(O2, E1);
    h2 W5 = __hmin2(O3, E2), W6 = __hmax2(O3, E2);

    // rank-7 of union(W sorted 8, V sorted 5)
    h2 med = W6;
    med = __hmin2(med, __hmax2(W1, V4));
    med = __hmin2(med, __hmax2(W2, V3));
    med = __hmin2(med, __hmax2(W3, V2));
    med = __hmin2(med, __hmax2(W4, V1));
    med = __hmin2(med, __hmax2(W5, V0));
    return med;
}

// Two medians (consecutive output rows) from 6 sorted rows R0..R5 (verified R5/R9).
__device__ __forceinline__ void median2(
    const h2 (&R0)[5], const h2 (&R1)[5], const h2 (&R2)[5],
    const h2 (&R3)[5], const h2 (&R4)[5], const h2 (&R5)[5],
    h2& medA, h2& medB)
{
    h2 a3A, a4A, a3B, a4B;
    {
        h2 p = R1[0], q = R2[0], rr = R3[0], ss = R4[0];
        h2 h1 = __hmax2(p, q), l1 = __hmin2(p, q);
        h2 hB = __hmax2(rr, ss), lB = __hmin2(rr, ss);
        h2 s3 = __hmax2(h1, hB);
        h2 s2 = __hmax2(__hmin2(h1, hB), __hmax2(l1, lB));
        h2 eA = R0[0], eB = R5[0];
        a4A = __hmax2(eA, s3); a3A = __hmax2(__hmin2(eA, s3), s2);
        a4B = __hmax2(eB, s3); a3B = __hmax2(__hmin2(eB, s3), s2);
    }
    h2 e0A, e1A, e0B, e1B;
    {
        h2 p = R1[4], q = R2[4], rr = R3[4], ss = R4[4];
        h2 h1 = __hmax2(p, q), l1 = __hmin2(p, q);
        h2 hB = __hmax2(rr, ss), lB = __hmin2(rr, ss);
        h2 s0 = __hmin2(l1, lB);
        h2 s1 = __hmin2(__hmax2(l1, lB), __hmin2(h1, hB));
        h2 eA = R0[4], eB = R5[4];
        e0A = __hmin2(eA, s0); e1A = __hmin2(__hmax2(eA, s0), s1);
        e0B = __hmin2(eB, s0); e1B = __hmin2(__hmax2(eB, s0), s1);
    }
    h2 b2A, b3A, b4A, b2B, b3B, b4B;
    {
        h2 a = R1[1], b = R2[1], c = R3[1], d = R4[1];
        cex(a, b); cex(c, d);
        h2 s3 = __hmax2(b, d), bm = __hmin2(b, d), cm = __hmax2(a, c);
        h2 s1 = __hmin2(bm, cm), s2 = __hmax2(bm, cm);
        h2 eA = R0[1], eB = R5[1];
        {
            h2 m = __hmin2(eA, s3); b4A = __hmax2(eA, s3);
            b3A = __hmax2(m, s2); h2 m2 = __hmin2(m, s2);
            b2A = __hmax2(m2, s1);
        }
        {
            h2 m = __hmin2(eB, s3); b4B = __hmax2(eB, s3);
            b3B = __hmax2(m, s2); h2 m2 = __hmin2(m, s2);
            b2B = __hmax2(m2, s1);
        }
    }
    h2 d0A, d1A, d2A, d0B, d1B, d2B;
    {
        h2 a = R1[3], b = R2[3], c = R3[3], d = R4[3];
        cex(a, b); cex(c, d);
        h2 s0 = __hmin2(a, c), cm = __hmax2(a, c), bm = __hmin2(b, d);
        h2 s1 = __hmin2(cm, bm), s2 = __hmax2(cm, bm);
        h2 eA = R0[3], eB = R5[3];
        {
            h2 m = __hmax2(eA, s0); d0A = __hmin2(eA, s0);
            d1A = __hmin2(m, s1); h2 m2 = __hmax2(m, s1);
            d2A = __hmin2(m2, s2);
        }
        {
            h2 m = __hmax2(eB, s0); d0B = __hmin2(eB, s0);
            d1B = __hmin2(m, s1); h2 m2 = __hmax2(m, s1);
            d2B = __hmin2(m2, s2);
        }
    }
    h2 c1A, c2A, c3A, c1B, c2B, c3B;
    {
        h2 a = R1[2], b = R2[2], c = R3[2], d = R4[2];
        sort4(a, b, c, d);
        h2 eA = R0[2], eB = R5[2];
        {
            h2 u = __hmax2(eA, a);
            c1A = __hmin2(u, b); u = __hmax2(u, b);
            c2A = __hmin2(u, c); u = __hmax2(u, c);
            c3A = __hmin2(u, d);
        }
        {
            h2 u = __hmax2(eB, a);
            c1B = __hmin2(u, b); u = __hmax2(u, b);
            c2B = __hmin2(u, c); u = __hmax2(u, c);
            c3B = __hmin2(u, d);
        }
    }
    medA = sel13(a3A, a4A, b2A, b3A, b4A, c1A, c2A, c3A, d0A, d1A, d2A, e0A, e1A);
    medB = sel13(a3B, a4B, b2B, b3B, b4B, c1B, c2B, c3B, d0B, d1B, d2B, e0B, e1B);
}

template <bool EDGE>
__device__ __forceinline__ void do_strip(const Taps& T, const float* __restrict__ sA,
                                         float* __restrict__ outb, int y0,
                                         int xm2, int xm1, int xc, int xp1, int xp2) {
    h2 r[6][5];

    #pragma unroll
    for (int i = 0; i < 4; i++) {
        float a[5], b[5];
        load_row2<EDGE>(T, sA, y0, -2 + i, xm2, xm1, xc, xp1, xp2, a, b);
        cvt_sort(a, b, r[i]);
    }

    #pragma unroll
    for (int tp = 0; tp < TROWS / 2; tp++) {
        {
            float a0[5], b0[5], a1[5], b1[5];
            load_row2<EDGE>(T, sA, y0, 2 * tp + 2, xm2, xm1, xc, xp1, xp2, a0, b0);
            load_row2<EDGE>(T, sA, y0, 2 * tp + 3, xm2, xm1, xc, xp1, xp2, a1, b1);
            cvt_sort(a0, b0, r[(2 * tp + 4) % 6]);
            cvt_sort(a1, b1, r[(2 * tp + 5) % 6]);
        }

        h2 medA, medB;
        median2(r[(2 * tp + 0) % 6], r[(2 * tp + 1) % 6], r[(2 * tp + 2) % 6],
                r[(2 * tp + 3) % 6], r[(2 * tp + 4) % 6], r[(2 * tp + 5) % 6],
                medA, medB);

        outb[(2 * tp) * IMG_W]                 = __low2float(medA)  * INV_SCALE;
        outb[(2 * tp) * IMG_W + PSTRIDE]       = __high2float(medA) * INV_SCALE;
        outb[(2 * tp + 1) * IMG_W]             = __low2float(medB)  * INV_SCALE;
        outb[(2 * tp + 1) * IMG_W + PSTRIDE]   = __high2float(medB) * INV_SCALE;
    }
}

__global__ void __launch_bounds__(128, 6)
median5x5_kernel(const float* __restrict__ src, float* __restrict__ dst) {
    const int tid   = blockIdx.x * blockDim.x + threadIdx.x;
    const int x     = tid & (IMG_W - 1);
    const int rest  = tid >> 9;                 // / 512
    const int strip = rest & (STRIPS - 1);      // % 32
    const int pair  = rest >> 5;                // / 32
    if (pair >= PAIRS) return;

    const float* sA = src + (size_t)(2 * pair) * PSTRIDE;
    float*       dA = dst + (size_t)(2 * pair) * PSTRIDE;

    const int xm2 = refl(x - 2, IMG_W);
    const int xm1 = refl(x - 1, IMG_W);
    const int xp1 = refl(x + 1, IMG_W);
    const int xp2 = refl(x + 2, IMG_W);
    const int y0  = strip * TROWS;

    const float* base = sA + y0 * IMG_W;
    Taps T{ base + xm2, base + xm1, base + x, base + xp1, base + xp2 };
    float* outb = dA + y0 * IMG_W + x;

    if (strip > 0 && strip < STRIPS - 1) {
        do_strip<false>(T, sA, outb, y0, xm2, xm1, x, xp1, xp2);
    } else {
        do_strip<true>(T, sA, outb, y0, xm2, xm1, x, xp1, xp2);
    }
}

extern "C" void kernel_launch(void* const* d_in, const int* in_sizes, int n_in,
                              void* d_out, int out_size) {
    (void)in_sizes; (void)n_in; (void)out_size;
    const float* src = (const float*)d_in[0];
    float*       dst = (float*)d_out;

    const int total_threads = PAIRS * IMG_W * STRIPS;   // 393216
    const int block = 128;
    const int grid  = total_threads / block;            // 3072
    median5x5_kernel<<<grid, block>>>(src, dst);
}